// round 3
// baseline (speedup 1.0000x reference)
#include <cuda_runtime.h>

typedef unsigned long long ull;

#define NHID 64
#define EXTD 32
#define KTOT 96
#define K2TOT 48          // KTOT/2 packed-k steps
#define MAXN 50000
#define TILE_E 128
#define LD2 130           // padded leading dim of A tile in float2 units

// Device scratch (allocation-free rule)
__device__ __align__(16) float g_M[192 * 64];      // W1 @ W2[:64]
__device__ __align__(16) float g_B[KTOT * 64];     // [Mb ; W2b] row-major [k][col]
__device__ __align__(16) float g_c[64];            // b1 @ W2[:64] + b2
__device__ __align__(16) float g_Pa[MAXN * 64];    // h @ Ma
__device__ __align__(16) float g_Pc[MAXN * 64];    // h @ Mc

__device__ __forceinline__ ull ffma2(ull a, ull b, ull c) {
    ull d;
    asm("fma.rn.f32x2 %0, %1, %2, %3;" : "=l"(d) : "l"(a), "l"(b), "l"(c));
    return d;
}
__device__ __forceinline__ ull pack2(float x, float y) {
    ull r;
    asm("mov.b64 %0, {%1, %2};" : "=l"(r) : "f"(x), "f"(y));
    return r;
}
__device__ __forceinline__ float2 unpack2(ull v) {
    float2 f;
    asm("mov.b64 {%0, %1}, %2;" : "=f"(f.x), "=f"(f.y) : "l"(v));
    return f;
}

// ---------------------------------------------------------------------------
// Kernel 0: compose. One output element per thread.
// ---------------------------------------------------------------------------
__global__ __launch_bounds__(256) void compose_kernel(const float* __restrict__ W1,
                                                      const float* __restrict__ b1,
                                                      const float* __restrict__ W2,
                                                      const float* __restrict__ b2) {
    int idx = blockIdx.x * blockDim.x + threadIdx.x;
    if (idx < 12288) {
        int r = idx >> 6, j = idx & 63;
        float s = 0.f;
#pragma unroll 16
        for (int k = 0; k < 64; ++k) s += W1[r * 64 + k] * W2[k * 64 + j];
        g_M[idx] = s;
        if (r >= 64 && r < 128) g_B[(r - 64) * 64 + j] = s;
    } else if (idx < 14336) {
        int t = idx - 12288;           // rows 64..95 of B
        g_B[64 * 64 + t] = W2[64 * 64 + t];
    } else if (idx < 14400) {
        int j = idx - 14336;
        float s = b2[j];
#pragma unroll 16
        for (int k = 0; k < 64; ++k) s += b1[k] * W2[k * 64 + j];
        g_c[j] = s;
    }
}

// ---------------------------------------------------------------------------
// Kernel 1: node projections Pa = h @ Ma, Pc = h @ Mc. Warp per node.
// ---------------------------------------------------------------------------
__global__ __launch_bounds__(256) void nodeproj_kernel(const float* __restrict__ h,
                                                       int nNodes) {
    __shared__ float sMa[64 * 64];
    __shared__ float sMc[64 * 64];
    int tid = threadIdx.x;
    for (int i = tid; i < 64 * 64; i += blockDim.x) {
        sMa[i] = g_M[i];
        sMc[i] = g_M[128 * 64 + i];
    }
    __syncthreads();

    int warp = tid >> 5, lane = tid & 31;
    int n = blockIdx.x * 8 + warp;
    if (n >= nNodes || n >= MAXN) return;

    float h0 = h[n * 64 + lane];
    float h1 = h[n * 64 + 32 + lane];
    float a0 = 0.f, a1 = 0.f, c0 = 0.f, c1 = 0.f;
#pragma unroll
    for (int k = 0; k < 64; ++k) {
        float hk = __shfl_sync(0xffffffffu, (k < 32) ? h0 : h1, k & 31);
        a0 += hk * sMa[k * 64 + lane];
        a1 += hk * sMa[k * 64 + 32 + lane];
        c0 += hk * sMc[k * 64 + lane];
        c1 += hk * sMc[k * 64 + 32 + lane];
    }
    g_Pa[n * 64 + lane] = a0;
    g_Pa[n * 64 + 32 + lane] = a1;
    g_Pc[n * 64 + lane] = c0;
    g_Pc[n * 64 + 32 + lane] = c1;
}

// ---------------------------------------------------------------------------
// Kernel 2: edge GEMM with packed f32x2 FMA, column-major lane layout.
// Warp w owns 16 consecutive edges (w*16..w*16+15), all 64 cols.
// Thread: 4 consecutive edges ((lane>>3)*4 + w*16 + 0..3) x 8 cols ((lane&7)*8).
//  -> B smem loads: 128B contiguous + broadcast across lane>>3 groups (~1 cyc)
//  -> A smem loads: 4 distinct 16B in a 128B window (~1-2 cyc)
//  -> epilogue gathers/stores: lanes 0-7 cover a full 256B row (8 wf/instr)
// ---------------------------------------------------------------------------
__global__ __launch_bounds__(256, 2) void edge_kernel(const float* __restrict__ e_h,
                                                      const float* __restrict__ ext,
                                                      const int* __restrict__ src,
                                                      const int* __restrict__ dst,
                                                      float* __restrict__ out,
                                                      int E) {
    extern __shared__ __align__(16) char smem[];
    ull* sA2 = (ull*)smem;                         // [K2TOT][LD2]
    ull* sB2 = sA2 + K2TOT * LD2;                  // [K2TOT][64]
    int* ssrc = (int*)(sB2 + K2TOT * 64);          // [TILE_E]
    int* sdst = ssrc + TILE_E;

    int tid = threadIdx.x;
    int base = blockIdx.x * TILE_E;

    // ---- Load A: e_h part (128 edges x 64 feats) -> k2 rows 0..31
#pragma unroll
    for (int it = 0; it < 8; ++it) {
        int p = tid + it * 256;        // 0..2047 float4s
        int e = p >> 4;
        int k0 = (p & 15) << 2;
        int ge = base + e;
        float4 v = make_float4(0.f, 0.f, 0.f, 0.f);
        if (ge < E) v = *(const float4*)&e_h[(long)ge * 64 + k0];
        int k2 = k0 >> 1;
        sA2[k2 * LD2 + e] = pack2(v.x, v.y);
        sA2[(k2 + 1) * LD2 + e] = pack2(v.z, v.w);
    }
    // ---- Load A: ext part (128 edges x 32 feats) -> k2 rows 32..47
#pragma unroll
    for (int it = 0; it < 4; ++it) {
        int p = tid + it * 256;        // 0..1023 float4s
        int e = p >> 3;
        int k0 = (p & 7) << 2;
        int ge = base + e;
        float4 v = make_float4(0.f, 0.f, 0.f, 0.f);
        if (ge < E) v = *(const float4*)&ext[(long)ge * 32 + k0];
        int k2 = 32 + (k0 >> 1);
        sA2[k2 * LD2 + e] = pack2(v.x, v.y);
        sA2[(k2 + 1) * LD2 + e] = pack2(v.z, v.w);
    }
    // ---- Load B packed: sB2[k2][c] = (B[2k2][c], B[2k2+1][c])
#pragma unroll
    for (int it = 0; it < 3; ++it) {
        int p = tid + it * 256;        // 48 k2 x 16 col4-groups
        int k2 = p >> 4;
        int c4 = (p & 15) << 2;
        float4 r0 = *(const float4*)&g_B[(2 * k2) * 64 + c4];
        float4 r1 = *(const float4*)&g_B[(2 * k2 + 1) * 64 + c4];
        sB2[k2 * 64 + c4 + 0] = pack2(r0.x, r1.x);
        sB2[k2 * 64 + c4 + 1] = pack2(r0.y, r1.y);
        sB2[k2 * 64 + c4 + 2] = pack2(r0.z, r1.z);
        sB2[k2 * 64 + c4 + 3] = pack2(r0.w, r1.w);
    }
    if (tid < TILE_E) {
        int ge = base + tid;
        ssrc[tid] = (ge < E) ? src[ge] : 0;
        sdst[tid] = (ge < E) ? dst[ge] : 0;
    }
    __syncthreads();

    int warp = tid >> 5;
    int lane = tid & 31;
    int e0 = warp * 16 + (lane >> 3) * 4;   // first of 4 consecutive local edges
    int c8 = (lane & 7) * 8;                // first of 8 consecutive cols

    ull acc[4][8];
#pragma unroll
    for (int i = 0; i < 4; ++i)
#pragma unroll
        for (int j = 0; j < 8; ++j) acc[i][j] = 0ull;

#pragma unroll 4
    for (int k2 = 0; k2 < K2TOT; ++k2) {
        const ull* arow = sA2 + k2 * LD2 + e0;
        ulonglong2 a01 = *(const ulonglong2*)(arow + 0);
        ulonglong2 a23 = *(const ulonglong2*)(arow + 2);
        const ull* brow = sB2 + k2 * 64 + c8;
        ulonglong2 b01 = *(const ulonglong2*)(brow + 0);
        ulonglong2 b23 = *(const ulonglong2*)(brow + 2);
        ulonglong2 b45 = *(const ulonglong2*)(brow + 4);
        ulonglong2 b67 = *(const ulonglong2*)(brow + 6);
        ull av[4] = {a01.x, a01.y, a23.x, a23.y};
        ull bv[8] = {b01.x, b01.y, b23.x, b23.y, b45.x, b45.y, b67.x, b67.y};
#pragma unroll
        for (int i = 0; i < 4; ++i)
#pragma unroll
            for (int j = 0; j < 8; ++j)
                acc[i][j] = ffma2(av[i], bv[j], acc[i][j]);
    }

    // ---- Epilogue: gather node projections, bias, relu, store (coalesced-ish)
    float4 cb0 = *(const float4*)&g_c[c8];
    float4 cb1 = *(const float4*)&g_c[c8 + 4];
#pragma unroll
    for (int i = 0; i < 4; ++i) {
        int le = e0 + i;
        int ge = base + le;
        if (ge < E) {
            int s = ssrc[le];
            int d = sdst[le];
            const float* pa = &g_Pa[(long)s * 64 + c8];
            const float* pc = &g_Pc[(long)d * 64 + c8];
            float4 pa0 = *(const float4*)pa;
            float4 pa1 = *(const float4*)(pa + 4);
            float4 pc0 = *(const float4*)pc;
            float4 pc1 = *(const float4*)(pc + 4);
            float r[8];
#pragma unroll
            for (int j = 0; j < 8; ++j) {
                float2 f = unpack2(acc[i][j]);
                r[j] = f.x + f.y;
            }
            float4 o0, o1;
            o0.x = fmaxf(r[0] + pa0.x + pc0.x + cb0.x, 0.f);
            o0.y = fmaxf(r[1] + pa0.y + pc0.y + cb0.y, 0.f);
            o0.z = fmaxf(r[2] + pa0.z + pc0.z + cb0.z, 0.f);
            o0.w = fmaxf(r[3] + pa0.w + pc0.w + cb0.w, 0.f);
            o1.x = fmaxf(r[4] + pa1.x + pc1.x + cb1.x, 0.f);
            o1.y = fmaxf(r[5] + pa1.y + pc1.y + cb1.y, 0.f);
            o1.z = fmaxf(r[6] + pa1.z + pc1.z + cb1.z, 0.f);
            o1.w = fmaxf(r[7] + pa1.w + pc1.w + cb1.w, 0.f);
            float* op = &out[(long)ge * 64 + c8];
            *(float4*)op = o0;
            *(float4*)(op + 4) = o1;
        }
    }
}

// ---------------------------------------------------------------------------
extern "C" void kernel_launch(void* const* d_in, const int* in_sizes, int n_in,
                              void* d_out, int out_size) {
    const float* h   = (const float*)d_in[0];
    const float* e_h = (const float*)d_in[1];
    const float* ext = (const float*)d_in[2];
    const float* W1  = (const float*)d_in[3];
    const float* b1  = (const float*)d_in[4];
    const float* W2  = (const float*)d_in[5];
    const float* b2  = (const float*)d_in[6];
    const int* src   = (const int*)d_in[7];
    const int* dst   = (const int*)d_in[8];
    float* out = (float*)d_out;

    int E = in_sizes[7];
    int N = in_sizes[0] / NHID;

    const int smem_bytes = (K2TOT * LD2 + K2TOT * 64) * (int)sizeof(ull)
                           + 2 * TILE_E * (int)sizeof(int);
    static int attr_done = 0;
    if (!attr_done) {
        cudaFuncSetAttribute(edge_kernel, cudaFuncAttributeMaxDynamicSharedMemorySize,
                             smem_bytes);
        attr_done = 1;
    }

    compose_kernel<<<(14400 + 255) / 256, 256>>>(W1, b1, W2, b2);
    nodeproj_kernel<<<(N + 7) / 8, 256>>>(h, N);
    edge_kernel<<<(E + TILE_E - 1) / TILE_E, 256, smem_bytes>>>(e_h, ext, src, dst, out, E);
}

// round 5
// speedup vs baseline: 1.9252x; 1.9252x over previous
#include <cuda_runtime.h>

typedef unsigned long long ull;

#define NHID 64
#define EXTD 32
#define KTOT 96
#define K2TOT 48          // KTOT/2 packed-k steps
#define MAXN 50000
#define TILE_E 128
#define LD2 130           // padded leading dim of A tile in float2 units

// Device scratch (allocation-free rule)
__device__ __align__(16) float g_M[192 * 64];      // W1 @ W2[:64]
__device__ __align__(16) float g_B[KTOT * 64];     // [Mb ; W2b] row-major [k][col]
__device__ __align__(16) float g_c[64];            // b1 @ W2[:64] + b2
__device__ __align__(16) float g_Pa[MAXN * 64];    // h @ Ma
__device__ __align__(16) float g_Pc[MAXN * 64];    // h @ Mc

__device__ __forceinline__ ull ffma2(ull a, ull b, ull c) {
    ull d;
    asm("fma.rn.f32x2 %0, %1, %2, %3;" : "=l"(d) : "l"(a), "l"(b), "l"(c));
    return d;
}
__device__ __forceinline__ ull pack2(float x, float y) {
    ull r;
    asm("mov.b64 %0, {%1, %2};" : "=l"(r) : "f"(x), "f"(y));
    return r;
}
__device__ __forceinline__ float2 unpack2(ull v) {
    float2 f;
    asm("mov.b64 {%0, %1}, %2;" : "=f"(f.x), "=f"(f.y) : "l"(v));
    return f;
}

// ---------------------------------------------------------------------------
// Kernel 0: compose. One output element per thread.
// ---------------------------------------------------------------------------
__global__ __launch_bounds__(256) void compose_kernel(const float* __restrict__ W1,
                                                      const float* __restrict__ b1,
                                                      const float* __restrict__ W2,
                                                      const float* __restrict__ b2) {
    int idx = blockIdx.x * blockDim.x + threadIdx.x;
    if (idx < 12288) {
        int r = idx >> 6, j = idx & 63;
        float s = 0.f;
#pragma unroll 16
        for (int k = 0; k < 64; ++k) s += W1[r * 64 + k] * W2[k * 64 + j];
        g_M[idx] = s;
        if (r >= 64 && r < 128) g_B[(r - 64) * 64 + j] = s;
    } else if (idx < 14336) {
        int t = idx - 12288;           // rows 64..95 of B
        g_B[64 * 64 + t] = W2[64 * 64 + t];
    } else if (idx < 14400) {
        int j = idx - 14336;
        float s = b2[j];
#pragma unroll 16
        for (int k = 0; k < 64; ++k) s += b1[k] * W2[k * 64 + j];
        g_c[j] = s;
    }
}

// ---------------------------------------------------------------------------
// Kernel 1: node projections Pa = h @ Ma, Pc = h @ Mc. Warp per node.
// ---------------------------------------------------------------------------
__global__ __launch_bounds__(256) void nodeproj_kernel(const float* __restrict__ h,
                                                       int nNodes) {
    __shared__ float sMa[64 * 64];
    __shared__ float sMc[64 * 64];
    int tid = threadIdx.x;
    for (int i = tid; i < 64 * 64; i += blockDim.x) {
        sMa[i] = g_M[i];
        sMc[i] = g_M[128 * 64 + i];
    }
    __syncthreads();

    int warp = tid >> 5, lane = tid & 31;
    int n = blockIdx.x * 8 + warp;
    if (n >= nNodes || n >= MAXN) return;

    float h0 = h[n * 64 + lane];
    float h1 = h[n * 64 + 32 + lane];
    float a0 = 0.f, a1 = 0.f, c0 = 0.f, c1 = 0.f;
#pragma unroll
    for (int k = 0; k < 64; ++k) {
        float hk = __shfl_sync(0xffffffffu, (k < 32) ? h0 : h1, k & 31);
        a0 += hk * sMa[k * 64 + lane];
        a1 += hk * sMa[k * 64 + 32 + lane];
        c0 += hk * sMc[k * 64 + lane];
        c1 += hk * sMc[k * 64 + 32 + lane];
    }
    g_Pa[n * 64 + lane] = a0;
    g_Pa[n * 64 + 32 + lane] = a1;
    g_Pc[n * 64 + lane] = c0;
    g_Pc[n * 64 + 32 + lane] = c1;
}

// ---------------------------------------------------------------------------
// Kernel 2: edge GEMM, packed f32x2 FMA.
// Warp footprint: 32-edge slab x 32-col half. Thread: 4 edges x 8 cols.
//   edges: slab + eg2*2 + {0,1}, slab + 16 + eg2*2 + {0,1}   (eg2 = lane&7)
//   cols:  ch + q*8 + cg2*2 + {0,1}, q=0..3                  (cg2 = lane>>3)
// All mainloop LDS.128 have their lanes inside one 128B segment (1 wf each).
// Epilogue: accs staged to XOR-swizzled smem, then coalesced gather/store
// where 16 lanes cover one full 256B Pa/Pc/out row.
// ---------------------------------------------------------------------------
__global__ __launch_bounds__(256, 2) void edge_kernel(const float* __restrict__ e_h,
                                                      const float* __restrict__ ext,
                                                      const int* __restrict__ src,
                                                      const int* __restrict__ dst,
                                                      float* __restrict__ out,
                                                      int E) {
    extern __shared__ __align__(16) char smem[];
    ull* sA2 = (ull*)smem;                         // [K2TOT][LD2]
    ull* sB2 = sA2 + K2TOT * LD2;                  // [K2TOT][64]
    int* ssrc = (int*)(sB2 + K2TOT * 64);          // [TILE_E]
    int* sdst = ssrc + TILE_E;
    float2* sO = (float2*)smem;                    // epilogue overlay [128][32]

    int tid = threadIdx.x;
    int base = blockIdx.x * TILE_E;

    // ---- Load A: e_h part (128 edges x 64 feats) -> k2 rows 0..31
#pragma unroll
    for (int it = 0; it < 8; ++it) {
        int p = tid + it * 256;        // 0..2047 float4s
        int e = p >> 4;
        int k0 = (p & 15) << 2;
        int ge = base + e;
        float4 v = make_float4(0.f, 0.f, 0.f, 0.f);
        if (ge < E) v = *(const float4*)&e_h[(long)ge * 64 + k0];
        int k2 = k0 >> 1;
        sA2[k2 * LD2 + e] = pack2(v.x, v.y);
        sA2[(k2 + 1) * LD2 + e] = pack2(v.z, v.w);
    }
    // ---- Load A: ext part (128 edges x 32 feats) -> k2 rows 32..47
#pragma unroll
    for (int it = 0; it < 4; ++it) {
        int p = tid + it * 256;        // 0..1023 float4s
        int e = p >> 3;
        int k0 = (p & 7) << 2;
        int ge = base + e;
        float4 v = make_float4(0.f, 0.f, 0.f, 0.f);
        if (ge < E) v = *(const float4*)&ext[(long)ge * 32 + k0];
        int k2 = 32 + (k0 >> 1);
        sA2[k2 * LD2 + e] = pack2(v.x, v.y);
        sA2[(k2 + 1) * LD2 + e] = pack2(v.z, v.w);
    }
    // ---- Load B packed: sB2[k2][c] = (B[2k2][c], B[2k2+1][c])
#pragma unroll
    for (int it = 0; it < 3; ++it) {
        int p = tid + it * 256;        // 48 k2 x 16 col4-groups
        int k2 = p >> 4;
        int c4 = (p & 15) << 2;
        float4 r0 = *(const float4*)&g_B[(2 * k2) * 64 + c4];
        float4 r1 = *(const float4*)&g_B[(2 * k2 + 1) * 64 + c4];
        sB2[k2 * 64 + c4 + 0] = pack2(r0.x, r1.x);
        sB2[k2 * 64 + c4 + 1] = pack2(r0.y, r1.y);
        sB2[k2 * 64 + c4 + 2] = pack2(r0.z, r1.z);
        sB2[k2 * 64 + c4 + 3] = pack2(r0.w, r1.w);
    }
    if (tid < TILE_E) {
        int ge = base + tid;
        ssrc[tid] = (ge < E) ? src[ge] : 0;
        sdst[tid] = (ge < E) ? dst[ge] : 0;
    }
    __syncthreads();

    int warp = tid >> 5;
    int lane = tid & 31;
    int slab = (warp & 3) * 32;        // edge slab base (local)
    int ch   = (warp >> 2) * 32;       // col half base (scalar cols)
    int eg2 = lane & 7;
    int cg2 = lane >> 3;

    ull acc[4][8];
#pragma unroll
    for (int i = 0; i < 4; ++i)
#pragma unroll
        for (int j = 0; j < 8; ++j) acc[i][j] = 0ull;

#pragma unroll 4
    for (int k2 = 0; k2 < K2TOT; ++k2) {
        const ull* arow = sA2 + k2 * LD2 + slab + eg2 * 2;
        ulonglong2 a01 = *(const ulonglong2*)(arow);        // edges +0,+1
        ulonglong2 a23 = *(const ulonglong2*)(arow + 16);   // edges +16,+17
        const ull* brow = sB2 + k2 * 64 + ch + cg2 * 2;
        ulonglong2 b0 = *(const ulonglong2*)(brow + 0);
        ulonglong2 b1 = *(const ulonglong2*)(brow + 8);
        ulonglong2 b2 = *(const ulonglong2*)(brow + 16);
        ulonglong2 b3 = *(const ulonglong2*)(brow + 24);
        ull av[4] = {a01.x, a01.y, a23.x, a23.y};
        ull bv[8] = {b0.x, b0.y, b1.x, b1.y, b2.x, b2.y, b3.x, b3.y};
#pragma unroll
        for (int i = 0; i < 4; ++i)
#pragma unroll
            for (int j = 0; j < 8; ++j)
                acc[i][j] = ffma2(av[i], bv[j], acc[i][j]);
    }

    // ---- Stage accs to swizzled smem (overlays sA2 region)
    __syncthreads();
    int swz = eg2 << 2;                // swizzle value for all 4 thread edges
#pragma unroll
    for (int i = 0; i < 4; ++i) {
        int le = slab + ((i < 2) ? (eg2 * 2 + i) : (16 + eg2 * 2 + (i - 2)));
#pragma unroll
        for (int q = 0; q < 4; ++q) {
            float2 f0 = unpack2(acc[i][q * 2]);
            float2 f1 = unpack2(acc[i][q * 2 + 1]);
            float2 v = make_float2(f0.x + f0.y, f1.x + f1.y);
            int c2 = (ch >> 1) + q * 4 + cg2;        // float2 col index 0..31
            sO[le * 32 + (c2 ^ swz)] = v;
        }
    }
    __syncthreads();

    // ---- Coalesced gather + bias + relu + store. 2 edges per round.
    int c4 = lane & 15;                // float4 col index 0..15
    int half = lane >> 4;
    float4 cb = *(const float4*)&g_c[c4 * 4];
#pragma unroll
    for (int r = 0; r < 8; ++r) {
        int le = warp * 16 + r * 2 + half;
        int swr = ((le >> 1) & 7) << 2;
        int sc2 = (c4 * 2) ^ swr;      // even -> float4 aligned
        float4 v = *(const float4*)&sO[le * 32 + sc2];
        int ge = base + le;
        if (ge < E) {
            int s = ssrc[le];
            int d = sdst[le];
            float4 pa = *(const float4*)&g_Pa[(long)s * 64 + c4 * 4];
            float4 pc = *(const float4*)&g_Pc[(long)d * 64 + c4 * 4];
            float4 o;
            o.x = fmaxf(v.x + pa.x + pc.x + cb.x, 0.f);
            o.y = fmaxf(v.y + pa.y + pc.y + cb.y, 0.f);
            o.z = fmaxf(v.z + pa.z + pc.z + cb.z, 0.f);
            o.w = fmaxf(v.w + pa.w + pc.w + cb.w, 0.f);
            *(float4*)&out[(long)ge * 64 + c4 * 4] = o;
        }
    }
}

// ---------------------------------------------------------------------------
extern "C" void kernel_launch(void* const* d_in, const int* in_sizes, int n_in,
                              void* d_out, int out_size) {
    const float* h   = (const float*)d_in[0];
    const float* e_h = (const float*)d_in[1];
    const float* ext = (const float*)d_in[2];
    const float* W1  = (const float*)d_in[3];
    const float* b1  = (const float*)d_in[4];
    const float* W2  = (const float*)d_in[5];
    const float* b2  = (const float*)d_in[6];
    const int* src   = (const int*)d_in[7];
    const int* dst   = (const int*)d_in[8];
    float* out = (float*)d_out;

    int E = in_sizes[7];
    int N = in_sizes[0] / NHID;

    const int smem_bytes = (K2TOT * LD2 + K2TOT * 64) * (int)sizeof(ull)
                           + 2 * TILE_E * (int)sizeof(int);
    static int attr_done = 0;
    if (!attr_done) {
        cudaFuncSetAttribute(edge_kernel, cudaFuncAttributeMaxDynamicSharedMemorySize,
                             smem_bytes);
        attr_done = 1;
    }

    compose_kernel<<<(14400 + 255) / 256, 256>>>(W1, b1, W2, b2);
    nodeproj_kernel<<<(N + 7) / 8, 256>>>(h, N);
    edge_kernel<<<(E + TILE_E - 1) / TILE_E, 256, smem_bytes>>>(e_h, ext, src, dst, out, E);
}